// round 14
// baseline (speedup 1.0000x reference)
#include <cuda_runtime.h>
#include <cuda_fp16.h>
#include <math.h>
#include <stdint.h>

#define B_   4
#define S_   2048
#define DIN  1024
#define H_   16
#define DH   64
#define M_   (B_ * S_)       // 8192
#define NTOT 3072
#define BH_  (B_ * H_)       // 64

// ---- scratch (device globals: allocation-free) ----
__device__ __half g_atth[M_ * H_ * DH];     // fp16 attention output [B*S, H*DH]

// fp16 attention operands, all [bh][s][e]
__device__ __half a_qh[BH_ * S_ * DH];      // pre-scaled by 0.125*log2(e)
__device__ __half a_kh[BH_ * S_ * DH];
__device__ __half a_vh[BH_ * S_ * DH];

// fp16 operands for QKV GEMM / O-proj
__device__ __half g_xh[M_ * DIN];
__device__ __half g_wh[NTOT * DIN];         // [n][k]
__device__ __half g_woh[DH * DIN];          // [n][k] for O-proj (n=64)

#define SCALE_LOG2E 0.18033688011112042591999058f  // 0.125 * log2(e)

// ============================================================================
// helpers
// ============================================================================
__device__ __forceinline__ uint32_t smem_u32(const void* p) {
    uint32_t a;
    asm("{ .reg .u64 t; cvta.to.shared.u64 t, %1; cvt.u32.u64 %0, t; }"
        : "=r"(a) : "l"(p));
    return a;
}
__device__ __forceinline__ void cp16(uint32_t dst, const void* src) {
    asm volatile("cp.async.cg.shared.global [%0], [%1], 16;" :: "r"(dst), "l"(src));
}
#define CP_COMMIT() asm volatile("cp.async.commit_group;" ::: "memory")
#define CP_WAIT(n)  asm volatile("cp.async.wait_group %0;" :: "n"(n) : "memory")

__device__ __forceinline__ void ldsm_x4(uint32_t* r, uint32_t addr) {
    asm volatile("ldmatrix.sync.aligned.m8n8.x4.shared.b16 {%0,%1,%2,%3}, [%4];"
                 : "=r"(r[0]), "=r"(r[1]), "=r"(r[2]), "=r"(r[3]) : "r"(addr));
}
__device__ __forceinline__ void ldsm_x4_t(uint32_t* r, uint32_t addr) {
    asm volatile("ldmatrix.sync.aligned.m8n8.x4.trans.shared.b16 {%0,%1,%2,%3}, [%4];"
                 : "=r"(r[0]), "=r"(r[1]), "=r"(r[2]), "=r"(r[3]) : "r"(addr));
}
__device__ __forceinline__ void mma_f16(float* c, const uint32_t* a, const uint32_t* b) {
    asm volatile(
        "mma.sync.aligned.m16n8k16.row.col.f32.f16.f16.f32 "
        "{%0,%1,%2,%3}, {%4,%5,%6,%7}, {%8,%9}, {%0,%1,%2,%3};"
        : "+f"(c[0]), "+f"(c[1]), "+f"(c[2]), "+f"(c[3])
        : "r"(a[0]), "r"(a[1]), "r"(a[2]), "r"(a[3]), "r"(b[0]), "r"(b[1]));
}

// exp2 on the MUFU pipe (1 instruction; frees FMA/ALU issue slots)
__device__ __forceinline__ float fexp2(float x) {
    float y;
    asm("ex2.approx.f32 %0, %1;" : "=f"(y) : "f"(x));
    return y;
}

__device__ __forceinline__ uint32_t pack_h2(float x, float y) {
    __half2 h = __floats2half2_rn(x, y);
    return *(uint32_t*)&h;
}

// ============================================================================
// merged conversion kernel: blocks [0,8192) convert X, [8192, 8976) weights
// ============================================================================
__global__ __launch_bounds__(256) void cvt_kernel(
    const float* __restrict__ x,
    const float* __restrict__ Wq, const float* __restrict__ Wk,
    const float* __restrict__ Wv, const float* __restrict__ Wo) {
    __shared__ float t[64][65];
    const int tid = threadIdx.x;

    if (blockIdx.x < 8192) {
        int i = (blockIdx.x * 256 + tid) * 4;
        float4 v = *(const float4*)&x[i];
        *(uint32_t*)&g_xh[i]     = pack_h2(v.x, v.y);
        *(uint32_t*)&g_xh[i + 2] = pack_h2(v.z, v.w);
        return;
    }

    const int bid = blockIdx.x - 8192;       // 0..783
    const int kc = bid & 15, g = bid >> 4;

    const float* src;
    __half* dst;
    if (g < 48) {
        int part = g >> 4, h = g & 15;
        const float* Wp = (part == 0) ? Wq : (part == 1) ? Wk : Wv;
        src = Wp + (size_t)h * (DIN * DH) + (size_t)kc * 64 * DH;
        dst = g_wh + (size_t)(part * 1024 + h * 64) * DIN + kc * 64;
    } else {
        src = Wo + (size_t)kc * 64 * DH;
        dst = g_woh + kc * 64;
    }

#pragma unroll
    for (int i = 0; i < 16; i++) {
        int idx = tid + i * 256;
        int kk = idx >> 6, e = idx & 63;
        t[kk][e] = src[kk * DH + e];
    }
    __syncthreads();
#pragma unroll
    for (int i = 0; i < 16; i++) {
        int idx = tid + i * 256;
        int e = idx >> 6, kk = idx & 63;
        dst[(size_t)e * DIN + kk] = __float2half_rn(t[kk][e]);
    }
}

// ============================================================================
// QKV GEMM, single-pass fp16 mma. 128-thread CTAs, 64x128 tile, BK=64
// (half the barriers of BK=32), 3-stage pipeline. Warp tile 64m x 32n.
// ============================================================================
#define BK      64
#define NCHUNK  (DIN / BK)     // 16
#define ROWB    144            // 128B data + 16B pad (proven conflict-free)
#define QA_SZ   9216           // 64 rows x 144B
#define QSTAGE  27648          // A 9216 + B 18432

__global__ __launch_bounds__(128) void qkv_mma_kernel(
    const float* __restrict__ bq, const float* __restrict__ bk,
    const float* __restrict__ bv)
{
    extern __shared__ __align__(128) char smem[];
    const uint32_t sb0 = smem_u32(smem);
    const int tid = threadIdx.x;
    const int wid = tid >> 5, l = tid & 31;
    const int wn = wid;                 // 1 x 4 warp grid
    const int bm = blockIdx.x;          // 0..127 (64 rows each)
    const int bn = blockIdx.y;          // 0..23

    const int arow0 = bm * 64, brow0 = bn * 128;

    uint32_t aoff[4], boff[2];
#pragma unroll
    for (int mi = 0; mi < 4; mi++) {
        int row = mi * 16 + (l & 15);
        int col = ((l >> 4) & 1) * 8;
        aoff[mi] = (uint32_t)(row * ROWB + col * 2);
    }
#pragma unroll
    for (int bg = 0; bg < 2; bg++) {
        int nrow = wn * 32 + bg * 16 + ((l >> 4) & 1) * 8 + (l & 7);
        int col = ((l >> 3) & 1) * 8;
        boff[bg] = (uint32_t)(nrow * ROWB + col * 2);
    }

    float acc[4][4][4];
#pragma unroll
    for (int i = 0; i < 4; i++)
#pragma unroll
        for (int j = 0; j < 4; j++)
#pragma unroll
            for (int q = 0; q < 4; q++) acc[i][j][q] = 0.0f;

    auto load_chunk = [&](int c, int s) {
        uint32_t base = sb0 + (uint32_t)s * QSTAGE;
#pragma unroll
        for (int i = 0; i < 4; i++) {
            int slot = tid + i * 128;          // 0..511 : A 64 rows x 8 kg
            int row = slot >> 3, kg = slot & 7;
            uint32_t so = (uint32_t)(row * ROWB + kg * 16);
            cp16(base + so, g_xh + (size_t)(arow0 + row) * DIN + c * BK + kg * 8);
        }
#pragma unroll
        for (int i = 0; i < 8; i++) {
            int slot = tid + i * 128;          // 0..1023 : B 128 rows x 8 kg
            int row = slot >> 3, kg = slot & 7;
            uint32_t so = (uint32_t)(row * ROWB + kg * 16);
            cp16(base + QA_SZ + so, g_wh + (size_t)(brow0 + row) * DIN + c * BK + kg * 8);
        }
    };

    load_chunk(0, 0);
    CP_COMMIT();
    load_chunk(1, 1);
    CP_COMMIT();

    for (int c = 0; c < NCHUNK; c++) {
        int s = c % 3;
        if (c == NCHUNK - 1) { CP_WAIT(0); } else { CP_WAIT(1); }
        __syncthreads();

        uint32_t base = sb0 + (uint32_t)s * QSTAGE;
#pragma unroll
        for (int ks = 0; ks < 4; ks++) {
            uint32_t kadd = (uint32_t)(ks * 32);
            uint32_t ah[4][4], bw[4][2];
#pragma unroll
            for (int mi = 0; mi < 4; mi++)
                ldsm_x4(ah[mi], base + aoff[mi] + kadd);
#pragma unroll
            for (int bg = 0; bg < 2; bg++) {
                uint32_t r[4];
                ldsm_x4(r, base + QA_SZ + boff[bg] + kadd);
                bw[bg * 2][0] = r[0]; bw[bg * 2][1] = r[1];
                bw[bg * 2 + 1][0] = r[2]; bw[bg * 2 + 1][1] = r[3];
            }
#pragma unroll
            for (int mi = 0; mi < 4; mi++)
#pragma unroll
                for (int ni = 0; ni < 4; ni++)
                    mma_f16(acc[mi][ni], ah[mi], bw[ni]);
        }

        if (c + 2 < NCHUNK) {
            load_chunk(c + 2, (c + 2) % 3);
            CP_COMMIT();
        }
    }

    const int part = bn >> 3;
    const float* __restrict__ bp = (part == 0) ? bq : (part == 1) ? bk : bv;
    __half* __restrict__ oh = (part == 0) ? a_qh : (part == 1) ? a_kh : a_vh;
    const int npart0 = (bn & 7) * 128 + wn * 32;
    const float scl = (part == 0) ? SCALE_LOG2E : 1.0f;

#pragma unroll
    for (int mi = 0; mi < 4; mi++) {
        int m0 = arow0 + mi * 16 + (l >> 2);
#pragma unroll
        for (int ni = 0; ni < 4; ni++) {
            int ncol = npart0 + ni * 8 + 2 * (l & 3);
            int h = ncol >> 6, e = ncol & 63;
            float b0 = bp[h * DH + e], b1 = bp[h * DH + e + 1];
#pragma unroll
            for (int half = 0; half < 2; half++) {
                int m = m0 + half * 8;
                int bb = m >> 11, sIdx = m & 2047;
                float v0 = (acc[mi][ni][half * 2 + 0] + b0) * scl;
                float v1 = (acc[mi][ni][half * 2 + 1] + b1) * scl;
                size_t idx = (((size_t)bb * H_ + h) * S_ + sIdx) * DH + e;
                *(uint32_t*)&oh[idx] = pack_h2(v0, v1);
            }
        }
    }
}

// ============================================================================
// Causal flash attention: 128-thread CTAs, 128-row q-tiles, warp tile
// 32 rows x 64 keys (2 m-frags share every K/V fragment). (R12 winner)
// ============================================================================
#define ARB    144
#define Q_O    0
#define QT_B   18432
#define STG_O  18432
#define V_O    9216
#define STG_SZ 18432
#define ATT_SMEM (QT_B + 2 * STG_SZ)   // 55296

__global__ __launch_bounds__(128) void attn_mma_kernel()
{
    extern __shared__ __align__(128) char smem[];
    const uint32_t sb = smem_u32(smem);
    const int tid = threadIdx.x;
    const int w = tid >> 5, l = tid & 31;
    const int bh = blockIdx.x;
    const int qt = 15 - blockIdx.y;

    const __half* __restrict__ qh = a_qh + (size_t)bh * S_ * DH;
    const __half* __restrict__ kh = a_kh + (size_t)bh * S_ * DH;
    const __half* __restrict__ vh = a_vh + (size_t)bh * S_ * DH;

#pragma unroll
    for (int i = 0; i < 8; i++) {
        int idx = tid + i * 128;
        int row = idx >> 3, kg = idx & 7;
        uint32_t so = (uint32_t)(row * ARB + kg * 16);
        cp16(sb + Q_O + so, qh + (size_t)(qt * 128 + row) * DH + kg * 8);
    }

    auto load_kv = [&](int kt, int s) {
        uint32_t base = sb + STG_O + (uint32_t)s * STG_SZ;
#pragma unroll
        for (int i = 0; i < 4; i++) {
            int idx = tid + i * 128;
            int row = idx >> 3, kg = idx & 7;
            uint32_t so = (uint32_t)(row * ARB + kg * 16);
            size_t go = (size_t)(kt * 64 + row) * DH + kg * 8;
            cp16(base + so,       kh + go);
            cp16(base + V_O + so, vh + go);
        }
    };

    const int nkt = 2 * qt + 2;
    load_kv(0, 0);
    CP_COMMIT();

    float o[2][8][4];
#pragma unroll
    for (int mi = 0; mi < 2; mi++)
#pragma unroll
        for (int i = 0; i < 8; i++)
#pragma unroll
            for (int j = 0; j < 4; j++) o[mi][i][j] = 0.0f;
    float mrow[4] = {-1e30f, -1e30f, -1e30f, -1e30f};
    float lrow[4] = {0.0f, 0.0f, 0.0f, 0.0f};

    int grow[4];
#pragma unroll
    for (int mi = 0; mi < 2; mi++) {
        grow[mi * 2]     = qt * 128 + w * 32 + mi * 16 + (l >> 2);
        grow[mi * 2 + 1] = grow[mi * 2] + 8;
    }
    uint32_t qa0[2];
#pragma unroll
    for (int mi = 0; mi < 2; mi++)
        qa0[mi] = sb + Q_O + (uint32_t)((w * 32 + mi * 16 + (l & 15)) * ARB
                                        + ((l >> 4) & 1) * 16);
    const uint32_t bsel = (uint32_t)((8 * ((l >> 4) & 1) + (l & 7)) * ARB
                                     + ((l >> 3) & 1) * 16);
    const uint32_t vsel = (uint32_t)(((((l >> 3) & 1) * 8) + (l & 7)) * ARB
                                     + ((l >> 4) & 1) * 16);

    uint32_t qf[2][4][4];

    for (int kt = 0; kt < nkt; kt++) {
        int s = kt & 1;
        CP_WAIT(0);
        __syncthreads();
        if (kt == 0) {
#pragma unroll
            for (int mi = 0; mi < 2; mi++)
#pragma unroll
                for (int ks = 0; ks < 4; ks++)
                    ldsm_x4(qf[mi][ks], qa0[mi] + ks * 32);
        }
        if (kt + 1 < nkt) {
            load_kv(kt + 1, 1 - s);
            CP_COMMIT();
        }
        uint32_t base = sb + STG_O + (uint32_t)s * STG_SZ;

        float sc[2][8][4];
#pragma unroll
        for (int mi = 0; mi < 2; mi++)
#pragma unroll
            for (int i = 0; i < 8; i++)
#pragma unroll
                for (int j = 0; j < 4; j++) sc[mi][i][j] = 0.0f;

#pragma unroll
        for (int ks = 0; ks < 4; ks++) {
#pragma unroll
            for (int nfp = 0; nfp < 4; nfp++) {
                uint32_t k4[4];
                ldsm_x4(k4, base + bsel + (uint32_t)(nfp * 16 * ARB + ks * 32));
#pragma unroll
                for (int mi = 0; mi < 2; mi++) {
                    mma_f16(sc[mi][2 * nfp],     qf[mi][ks], k4);
                    mma_f16(sc[mi][2 * nfp + 1], qf[mi][ks], k4 + 2);
                }
            }
        }

        if (kt >= 2 * qt) {
#pragma unroll
            for (int mi = 0; mi < 2; mi++)
#pragma unroll
                for (int nf = 0; nf < 8; nf++) {
                    int gc = kt * 64 + nf * 8 + 2 * (l & 3);
                    if (gc     > grow[mi * 2])     sc[mi][nf][0] = -1e30f;
                    if (gc + 1 > grow[mi * 2])     sc[mi][nf][1] = -1e30f;
                    if (gc     > grow[mi * 2 + 1]) sc[mi][nf][2] = -1e30f;
                    if (gc + 1 > grow[mi * 2 + 1]) sc[mi][nf][3] = -1e30f;
                }
        }

#pragma unroll
        for (int mi = 0; mi < 2; mi++) {
            float mx0 = -1e30f, mx1 = -1e30f;
#pragma unroll
            for (int nf = 0; nf < 8; nf++) {
                mx0 = fmaxf(mx0, fmaxf(sc[mi][nf][0], sc[mi][nf][1]));
                mx1 = fmaxf(mx1, fmaxf(sc[mi][nf][2], sc[mi][nf][3]));
            }
#pragma unroll
            for (int off = 1; off < 4; off <<= 1) {
                mx0 = fmaxf(mx0, __shfl_xor_sync(0xffffffffu, mx0, off));
                mx1 = fmaxf(mx1, __shfl_xor_sync(0xffffffffu, mx1, off));
            }
            float mn0 = fmaxf(mrow[mi * 2], mx0);
            float mn1 = fmaxf(mrow[mi * 2 + 1], mx1);
            float al0 = fexp2(mrow[mi * 2] - mn0);
            float al1 = fexp2(mrow[mi * 2 + 1] - mn1);
            mrow[mi * 2] = mn0; mrow[mi * 2 + 1] = mn1;

            float rs0 = 0.0f, rs1 = 0.0f;
#pragma unroll
            for (int nf = 0; nf < 8; nf++) {
                sc[mi][nf][0] = fexp2(sc[mi][nf][0] - mn0);
                sc[mi][nf][1] = fexp2(sc[mi][nf][1] - mn0);
                sc[mi][nf][2] = fexp2(sc[mi][nf][2] - mn1);
                sc[mi][nf][3] = fexp2(sc[mi][nf][3] - mn1);
                rs0 += sc[mi][nf][0] + sc[mi][nf][1];
                rs1 += sc[mi][nf][2] + sc[mi][nf][3];
            }
#pragma unroll
            for (int off = 1; off < 4; off <<= 1) {
                rs0 += __shfl_xor_sync(0xffffffffu, rs0, off);
                rs1 += __shfl_xor_sync(0xffffffffu, rs1, off);
            }
            lrow[mi * 2]     = lrow[mi * 2] * al0 + rs0;
            lrow[mi * 2 + 1] = lrow[mi * 2 + 1] * al1 + rs1;
#pragma unroll
            for (int nf = 0; nf < 8; nf++) {
                o[mi][nf][0] *= al0; o[mi][nf][1] *= al0;
                o[mi][nf][2] *= al1; o[mi][nf][3] *= al1;
            }
        }

        uint32_t ph[2][4][4];
#pragma unroll
        for (int mi = 0; mi < 2; mi++)
#pragma unroll
            for (int ks = 0; ks < 4; ks++) {
                ph[mi][ks][0] = pack_h2(sc[mi][2 * ks][0],     sc[mi][2 * ks][1]);
                ph[mi][ks][1] = pack_h2(sc[mi][2 * ks][2],     sc[mi][2 * ks][3]);
                ph[mi][ks][2] = pack_h2(sc[mi][2 * ks + 1][0], sc[mi][2 * ks + 1][1]);
                ph[mi][ks][3] = pack_h2(sc[mi][2 * ks + 1][2], sc[mi][2 * ks + 1][3]);
            }

#pragma unroll
        for (int ks = 0; ks < 4; ks++) {
#pragma unroll
            for (int np = 0; np < 4; np++) {
                uint32_t v4[4];
                ldsm_x4_t(v4, base + V_O + vsel
                              + (uint32_t)(ks * 16 * ARB + np * 32));
#pragma unroll
                for (int mi = 0; mi < 2; mi++) {
                    mma_f16(o[mi][2 * np],     ph[mi][ks], v4);
                    mma_f16(o[mi][2 * np + 1], ph[mi][ks], v4 + 2);
                }
            }
        }
    }

    const int b = bh >> 4, h = bh & 15;
#pragma unroll
    for (int mi = 0; mi < 2; mi++) {
        float inv0 = 1.0f / lrow[mi * 2], inv1 = 1.0f / lrow[mi * 2 + 1];
        size_t r0 = (size_t)(b * S_ + grow[mi * 2]) * (H_ * DH) + h * DH;
        size_t r1 = (size_t)(b * S_ + grow[mi * 2 + 1]) * (H_ * DH) + h * DH;
#pragma unroll
        for (int nf = 0; nf < 8; nf++) {
            int e = nf * 8 + 2 * (l & 3);
            *(uint32_t*)&g_atth[r0 + e] = pack_h2(o[mi][nf][0] * inv0,
                                                  o[mi][nf][1] * inv0);
            *(uint32_t*)&g_atth[r1 + e] = pack_h2(o[mi][nf][2] * inv1,
                                                  o[mi][nf][3] * inv1);
        }
    }
}

// ============================================================================
// O-projection via fp16 mma: out[8192,64] = att[8192,1024] @ Wo + bo
// (BK=32 pipeline; ROWB2=80 local layout)
// ============================================================================
#define OPBK     32
#define OPNCH    (DIN / OPBK)
#define ROWB2    80
#define OP_BW    10240
#define OP_STAGE 15360       // A 10240 + B 5120

__global__ __launch_bounds__(256) void oproj_mma_kernel(
    const float* __restrict__ bo, float* __restrict__ out)
{
    extern __shared__ __align__(128) char smem[];
    const uint32_t sb0 = smem_u32(smem);
    const int tid = threadIdx.x;
    const int wid = tid >> 5, l = tid & 31;
    const int wm = wid & 1, wn = wid >> 1;
    const int bm = blockIdx.x;
    const int arow0 = bm * 128;

    uint32_t aoff[4], boff;
#pragma unroll
    for (int mi = 0; mi < 4; mi++) {
        int row = wm * 64 + mi * 16 + (l & 15);
        int col = ((l >> 4) & 1) * 8;
        aoff[mi] = (uint32_t)(row * ROWB2 + col * 2);
    }
    {
        int nrow = wn * 16 + ((l >> 4) & 1) * 8 + (l & 7);
        int col = ((l >> 3) & 1) * 8;
        boff = (uint32_t)(nrow * ROWB2 + col * 2);
    }

    float acc[4][2][4];
#pragma unroll
    for (int i = 0; i < 4; i++)
#pragma unroll
        for (int j = 0; j < 2; j++)
#pragma unroll
            for (int q = 0; q < 4; q++) acc[i][j][q] = 0.0f;

    auto load_chunk = [&](int c, int s) {
        uint32_t base = sb0 + (uint32_t)s * OP_STAGE;
#pragma unroll
        for (int i = 0; i < 2; i++) {
            int slot = tid + i * 256;
            int row = slot >> 2, kg = slot & 3;
            uint32_t so = (uint32_t)(row * ROWB2 + kg * 16);
            cp16(base + so, g_atth + (size_t)(arow0 + row) * DIN + c * OPBK + kg * 8);
        }
        {
            int row = tid >> 2, kg = tid & 3;
            uint32_t so = (uint32_t)(row * ROWB2 + kg * 16);
            cp16(base + OP_BW + so, g_woh + (size_t)row * DIN + c * OPBK + kg * 8);
        }
    };

    load_chunk(0, 0);
    CP_COMMIT();
    load_chunk(1, 1);
    CP_COMMIT();

    for (int c = 0; c < OPNCH; c++) {
        int s = c % 3;
        if (c == OPNCH - 1) { CP_WAIT(0); } else { CP_WAIT(1); }
        __syncthreads();

        uint32_t base = sb0 + (uint32_t)s * OP_STAGE;
#pragma unroll
        for (int ks = 0; ks < 2; ks++) {
            uint32_t kadd = (uint32_t)(ks * 32);
            uint32_t ah[4][4], bw[2][2];
#pragma unroll
            for (int mi = 0; mi < 4; mi++)
                ldsm_x4(ah[mi], base + aoff[mi] + kadd);
            {
                uint32_t r[4];
                ldsm_x4(r, base + OP_BW + boff + kadd);
                bw[0][0] = r[0]; bw[0][1] = r[1];
                bw[1][0] = r[2]; bw[1][1] = r[3];
            }
#pragma unroll
            for (int mi = 0; mi < 4; mi++)
#pragma unroll
                for (int ni = 0; ni < 2; ni++)
                    mma_f16(acc[mi][ni], ah[mi], bw[ni]);
        }

        if (c + 2 < OPNCH) {
            load_chunk(c + 2, (c + 2) % 3);
            CP_COMMIT();
        }
    }

#pragma unroll
    for (int mi = 0; mi < 4; mi++) {
        int m0 = arow0 + wm * 64 + mi * 16 + (l >> 2);
#pragma unroll
        for (int ni = 0; ni < 2; ni++) {
            int ncol = wn * 16 + ni * 8 + 2 * (l & 3);
            float b0 = bo[ncol], b1 = bo[ncol + 1];
#pragma unroll
            for (int half = 0; half < 2; half++) {
                int m = m0 + half * 8;
                float2 v;
                v.x = acc[mi][ni][half * 2 + 0] + b0;
                v.y = acc[mi][ni][half * 2 + 1] + b1;
                *(float2*)&out[(size_t)m * DH + ncol] = v;
            }
        }
    }
}

// ============================================================================
extern "C" void kernel_launch(void* const* d_in, const int* in_sizes, int n_in,
                              void* d_out, int out_size)
{
    const float* x  = (const float*)d_in[0];
    const float* Wq = (const float*)d_in[1];
    const float* bq = (const float*)d_in[2];
    const float* Wk = (const float*)d_in[3];
    const float* bk = (const float*)d_in[4];
    const float* Wv = (const float*)d_in[5];
    const float* bv = (const float*)d_in[6];
    const float* Wo = (const float*)d_in[7];
    const float* bo = (const float*)d_in[8];
    float* out = (float*)d_out;

    cudaFuncSetAttribute(qkv_mma_kernel, cudaFuncAttributeMaxDynamicSharedMemorySize,
                         3 * QSTAGE);
    cudaFuncSetAttribute(attn_mma_kernel, cudaFuncAttributeMaxDynamicSharedMemorySize,
                         ATT_SMEM);
    cudaFuncSetAttribute(oproj_mma_kernel, cudaFuncAttributeMaxDynamicSharedMemorySize,
                         3 * OP_STAGE);

    cvt_kernel<<<8976, 256>>>(x, Wq, Wk, Wv, Wo);
    qkv_mma_kernel<<<dim3(128, 24), 128, 3 * QSTAGE>>>(bq, bk, bv);
    attn_mma_kernel<<<dim3(64, 16), 128, ATT_SMEM>>>();
    oproj_mma_kernel<<<M_ / 128, 256, 3 * OP_STAGE>>>(bo, out);
}

// round 15
// speedup vs baseline: 1.0667x; 1.0667x over previous
#include <cuda_runtime.h>
#include <cuda_fp16.h>
#include <math.h>
#include <stdint.h>

#define B_   4
#define S_   2048
#define DIN  1024
#define H_   16
#define DH   64
#define M_   (B_ * S_)       // 8192
#define NTOT 3072
#define BH_  (B_ * H_)       // 64

// ---- scratch (device globals: allocation-free) ----
__device__ __half g_atth[M_ * H_ * DH];     // fp16 attention output [B*S, H*DH]

// fp16 attention operands, all [bh][s][e]
__device__ __half a_qh[BH_ * S_ * DH];      // pre-scaled by 0.125*log2(e)
__device__ __half a_kh[BH_ * S_ * DH];
__device__ __half a_vh[BH_ * S_ * DH];

// fp16 operands for QKV GEMM / O-proj
__device__ __half g_xh[M_ * DIN];
__device__ __half g_wh[NTOT * DIN];         // [n][k]
__device__ __half g_woh[DH * DIN];          // [n][k] for O-proj (n=64)

#define SCALE_LOG2E 0.18033688011112042591999058f  // 0.125 * log2(e)

// ============================================================================
// helpers
// ============================================================================
__device__ __forceinline__ uint32_t smem_u32(const void* p) {
    uint32_t a;
    asm("{ .reg .u64 t; cvta.to.shared.u64 t, %1; cvt.u32.u64 %0, t; }"
        : "=r"(a) : "l"(p));
    return a;
}
__device__ __forceinline__ void cp16(uint32_t dst, const void* src) {
    asm volatile("cp.async.cg.shared.global [%0], [%1], 16;" :: "r"(dst), "l"(src));
}
#define CP_COMMIT() asm volatile("cp.async.commit_group;" ::: "memory")
#define CP_WAIT(n)  asm volatile("cp.async.wait_group %0;" :: "n"(n) : "memory")

__device__ __forceinline__ void ldsm_x4(uint32_t* r, uint32_t addr) {
    asm volatile("ldmatrix.sync.aligned.m8n8.x4.shared.b16 {%0,%1,%2,%3}, [%4];"
                 : "=r"(r[0]), "=r"(r[1]), "=r"(r[2]), "=r"(r[3]) : "r"(addr));
}
__device__ __forceinline__ void ldsm_x4_t(uint32_t* r, uint32_t addr) {
    asm volatile("ldmatrix.sync.aligned.m8n8.x4.trans.shared.b16 {%0,%1,%2,%3}, [%4];"
                 : "=r"(r[0]), "=r"(r[1]), "=r"(r[2]), "=r"(r[3]) : "r"(addr));
}
__device__ __forceinline__ void mma_f16(float* c, const uint32_t* a, const uint32_t* b) {
    asm volatile(
        "mma.sync.aligned.m16n8k16.row.col.f32.f16.f16.f32 "
        "{%0,%1,%2,%3}, {%4,%5,%6,%7}, {%8,%9}, {%0,%1,%2,%3};"
        : "+f"(c[0]), "+f"(c[1]), "+f"(c[2]), "+f"(c[3])
        : "r"(a[0]), "r"(a[1]), "r"(a[2]), "r"(a[3]), "r"(b[0]), "r"(b[1]));
}

// exp2 on the MUFU pipe (1 instruction; frees FMA/ALU issue slots)
__device__ __forceinline__ float fexp2(float x) {
    float y;
    asm("ex2.approx.f32 %0, %1;" : "=f"(y) : "f"(x));
    return y;
}

__device__ __forceinline__ uint32_t pack_h2(float x, float y) {
    __half2 h = __floats2half2_rn(x, y);
    return *(uint32_t*)&h;
}

// ============================================================================
// merged conversion kernel: blocks [0,8192) convert X, [8192, 8976) weights
// ============================================================================
__global__ __launch_bounds__(256) void cvt_kernel(
    const float* __restrict__ x,
    const float* __restrict__ Wq, const float* __restrict__ Wk,
    const float* __restrict__ Wv, const float* __restrict__ Wo) {
    __shared__ float t[64][65];
    const int tid = threadIdx.x;

    if (blockIdx.x < 8192) {
        int i = (blockIdx.x * 256 + tid) * 4;
        float4 v = *(const float4*)&x[i];
        *(uint32_t*)&g_xh[i]     = pack_h2(v.x, v.y);
        *(uint32_t*)&g_xh[i + 2] = pack_h2(v.z, v.w);
        return;
    }

    const int bid = blockIdx.x - 8192;       // 0..783
    const int kc = bid & 15, g = bid >> 4;

    const float* src;
    __half* dst;
    if (g < 48) {
        int part = g >> 4, h = g & 15;
        const float* Wp = (part == 0) ? Wq : (part == 1) ? Wk : Wv;
        src = Wp + (size_t)h * (DIN * DH) + (size_t)kc * 64 * DH;
        dst = g_wh + (size_t)(part * 1024 + h * 64) * DIN + kc * 64;
    } else {
        src = Wo + (size_t)kc * 64 * DH;
        dst = g_woh + kc * 64;
    }

#pragma unroll
    for (int i = 0; i < 16; i++) {
        int idx = tid + i * 256;
        int kk = idx >> 6, e = idx & 63;
        t[kk][e] = src[kk * DH + e];
    }
    __syncthreads();
#pragma unroll
    for (int i = 0; i < 16; i++) {
        int idx = tid + i * 256;
        int e = idx >> 6, kk = idx & 63;
        dst[(size_t)e * DIN + kk] = __float2half_rn(t[kk][e]);
    }
}

// ============================================================================
// QKV GEMM, single-pass fp16 mma. 128-thread CTAs, 64x128 tile, BK=32,
// 3-stage pipeline. Warp tile 64m x 32n. (R12 312.4us winner, verbatim)
// ============================================================================
#define BK      32
#define NCHUNK  (DIN / BK)
#define ROWB    80
#define QA_SZ   5120           // 64 rows x 80B
#define QSTAGE  15360          // A 5120 + B 10240

__global__ __launch_bounds__(128) void qkv_mma_kernel(
    const float* __restrict__ bq, const float* __restrict__ bk,
    const float* __restrict__ bv)
{
    extern __shared__ __align__(128) char smem[];
    const uint32_t sb0 = smem_u32(smem);
    const int tid = threadIdx.x;
    const int wid = tid >> 5, l = tid & 31;
    const int wn = wid;                 // 1 x 4 warp grid
    const int bm = blockIdx.x;          // 0..127 (64 rows each)
    const int bn = blockIdx.y;          // 0..23

    const int arow0 = bm * 64, brow0 = bn * 128;

    uint32_t aoff[4], boff[2];
#pragma unroll
    for (int mi = 0; mi < 4; mi++) {
        int row = mi * 16 + (l & 15);
        int col = ((l >> 4) & 1) * 8;
        aoff[mi] = (uint32_t)(row * ROWB + col * 2);
    }
#pragma unroll
    for (int bg = 0; bg < 2; bg++) {
        int nrow = wn * 32 + bg * 16 + ((l >> 4) & 1) * 8 + (l & 7);
        int col = ((l >> 3) & 1) * 8;
        boff[bg] = (uint32_t)(nrow * ROWB + col * 2);
    }

    float acc[4][4][4];
#pragma unroll
    for (int i = 0; i < 4; i++)
#pragma unroll
        for (int j = 0; j < 4; j++)
#pragma unroll
            for (int q = 0; q < 4; q++) acc[i][j][q] = 0.0f;

    auto load_chunk = [&](int c, int s) {
        uint32_t base = sb0 + (uint32_t)s * QSTAGE;
#pragma unroll
        for (int i = 0; i < 2; i++) {
            int slot = tid + i * 128;          // 0..255 : A 64 rows x 4 kg
            int row = slot >> 2, kg = slot & 3;
            uint32_t so = (uint32_t)(row * ROWB + kg * 16);
            cp16(base + so, g_xh + (size_t)(arow0 + row) * DIN + c * BK + kg * 8);
        }
#pragma unroll
        for (int i = 0; i < 4; i++) {
            int slot = tid + i * 128;          // 0..511 : B 128 rows x 4 kg
            int row = slot >> 2, kg = slot & 3;
            uint32_t so = (uint32_t)(row * ROWB + kg * 16);
            cp16(base + QA_SZ + so, g_wh + (size_t)(brow0 + row) * DIN + c * BK + kg * 8);
        }
    };

    load_chunk(0, 0);
    CP_COMMIT();
    load_chunk(1, 1);
    CP_COMMIT();

    for (int c = 0; c < NCHUNK; c++) {
        int s = c % 3;
        if (c == NCHUNK - 1) { CP_WAIT(0); } else { CP_WAIT(1); }
        __syncthreads();

        uint32_t base = sb0 + (uint32_t)s * QSTAGE;
#pragma unroll
        for (int ks = 0; ks < 2; ks++) {
            uint32_t kadd = (uint32_t)(ks * 32);
            uint32_t ah[4][4], bw[4][2];
#pragma unroll
            for (int mi = 0; mi < 4; mi++)
                ldsm_x4(ah[mi], base + aoff[mi] + kadd);
#pragma unroll
            for (int bg = 0; bg < 2; bg++) {
                uint32_t r[4];
                ldsm_x4(r, base + QA_SZ + boff[bg] + kadd);
                bw[bg * 2][0] = r[0]; bw[bg * 2][1] = r[1];
                bw[bg * 2 + 1][0] = r[2]; bw[bg * 2 + 1][1] = r[3];
            }
#pragma unroll
            for (int mi = 0; mi < 4; mi++)
#pragma unroll
                for (int ni = 0; ni < 4; ni++)
                    mma_f16(acc[mi][ni], ah[mi], bw[ni]);
        }

        if (c + 2 < NCHUNK) {
            load_chunk(c + 2, (c + 2) % 3);
            CP_COMMIT();
        }
    }

    const int part = bn >> 3;
    const float* __restrict__ bp = (part == 0) ? bq : (part == 1) ? bk : bv;
    __half* __restrict__ oh = (part == 0) ? a_qh : (part == 1) ? a_kh : a_vh;
    const int npart0 = (bn & 7) * 128 + wn * 32;
    const float scl = (part == 0) ? SCALE_LOG2E : 1.0f;

#pragma unroll
    for (int mi = 0; mi < 4; mi++) {
        int m0 = arow0 + mi * 16 + (l >> 2);
#pragma unroll
        for (int ni = 0; ni < 4; ni++) {
            int ncol = npart0 + ni * 8 + 2 * (l & 3);
            int h = ncol >> 6, e = ncol & 63;
            float b0 = bp[h * DH + e], b1 = bp[h * DH + e + 1];
#pragma unroll
            for (int half = 0; half < 2; half++) {
                int m = m0 + half * 8;
                int bb = m >> 11, sIdx = m & 2047;
                float v0 = (acc[mi][ni][half * 2 + 0] + b0) * scl;
                float v1 = (acc[mi][ni][half * 2 + 1] + b1) * scl;
                size_t idx = (((size_t)bb * H_ + h) * S_ + sIdx) * DH + e;
                *(uint32_t*)&oh[idx] = pack_h2(v0, v1);
            }
        }
    }
}

// ============================================================================
// Causal flash attention: 128-thread CTAs, 128-row q-tiles, warp tile
// 32 rows x 64 keys (2 m-frags share every K/V fragment). (R12 winner)
// ============================================================================
#define ARB    144
#define Q_O    0
#define QT_B   18432
#define STG_O  18432
#define V_O    9216
#define STG_SZ 18432
#define ATT_SMEM (QT_B + 2 * STG_SZ)   // 55296

__global__ __launch_bounds__(128) void attn_mma_kernel()
{
    extern __shared__ __align__(128) char smem[];
    const uint32_t sb = smem_u32(smem);
    const int tid = threadIdx.x;
    const int w = tid >> 5, l = tid & 31;
    const int bh = blockIdx.x;
    const int qt = 15 - blockIdx.y;

    const __half* __restrict__ qh = a_qh + (size_t)bh * S_ * DH;
    const __half* __restrict__ kh = a_kh + (size_t)bh * S_ * DH;
    const __half* __restrict__ vh = a_vh + (size_t)bh * S_ * DH;

#pragma unroll
    for (int i = 0; i < 8; i++) {
        int idx = tid + i * 128;
        int row = idx >> 3, kg = idx & 7;
        uint32_t so = (uint32_t)(row * ARB + kg * 16);
        cp16(sb + Q_O + so, qh + (size_t)(qt * 128 + row) * DH + kg * 8);
    }

    auto load_kv = [&](int kt, int s) {
        uint32_t base = sb + STG_O + (uint32_t)s * STG_SZ;
#pragma unroll
        for (int i = 0; i < 4; i++) {
            int idx = tid + i * 128;
            int row = idx >> 3, kg = idx & 7;
            uint32_t so = (uint32_t)(row * ARB + kg * 16);
            size_t go = (size_t)(kt * 64 + row) * DH + kg * 8;
            cp16(base + so,       kh + go);
            cp16(base + V_O + so, vh + go);
        }
    };

    const int nkt = 2 * qt + 2;
    load_kv(0, 0);
    CP_COMMIT();

    float o[2][8][4];
#pragma unroll
    for (int mi = 0; mi < 2; mi++)
#pragma unroll
        for (int i = 0; i < 8; i++)
#pragma unroll
            for (int j = 0; j < 4; j++) o[mi][i][j] = 0.0f;
    float mrow[4] = {-1e30f, -1e30f, -1e30f, -1e30f};
    float lrow[4] = {0.0f, 0.0f, 0.0f, 0.0f};

    int grow[4];
#pragma unroll
    for (int mi = 0; mi < 2; mi++) {
        grow[mi * 2]     = qt * 128 + w * 32 + mi * 16 + (l >> 2);
        grow[mi * 2 + 1] = grow[mi * 2] + 8;
    }
    uint32_t qa0[2];
#pragma unroll
    for (int mi = 0; mi < 2; mi++)
        qa0[mi] = sb + Q_O + (uint32_t)((w * 32 + mi * 16 + (l & 15)) * ARB
                                        + ((l >> 4) & 1) * 16);
    const uint32_t bsel = (uint32_t)((8 * ((l >> 4) & 1) + (l & 7)) * ARB
                                     + ((l >> 3) & 1) * 16);
    const uint32_t vsel = (uint32_t)(((((l >> 3) & 1) * 8) + (l & 7)) * ARB
                                     + ((l >> 4) & 1) * 16);

    uint32_t qf[2][4][4];

    for (int kt = 0; kt < nkt; kt++) {
        int s = kt & 1;
        CP_WAIT(0);
        __syncthreads();
        if (kt == 0) {
#pragma unroll
            for (int mi = 0; mi < 2; mi++)
#pragma unroll
                for (int ks = 0; ks < 4; ks++)
                    ldsm_x4(qf[mi][ks], qa0[mi] + ks * 32);
        }
        if (kt + 1 < nkt) {
            load_kv(kt + 1, 1 - s);
            CP_COMMIT();
        }
        uint32_t base = sb + STG_O + (uint32_t)s * STG_SZ;

        float sc[2][8][4];
#pragma unroll
        for (int mi = 0; mi < 2; mi++)
#pragma unroll
            for (int i = 0; i < 8; i++)
#pragma unroll
                for (int j = 0; j < 4; j++) sc[mi][i][j] = 0.0f;

#pragma unroll
        for (int ks = 0; ks < 4; ks++) {
#pragma unroll
            for (int nfp = 0; nfp < 4; nfp++) {
                uint32_t k4[4];
                ldsm_x4(k4, base + bsel + (uint32_t)(nfp * 16 * ARB + ks * 32));
#pragma unroll
                for (int mi = 0; mi < 2; mi++) {
                    mma_f16(sc[mi][2 * nfp],     qf[mi][ks], k4);
                    mma_f16(sc[mi][2 * nfp + 1], qf[mi][ks], k4 + 2);
                }
            }
        }

        if (kt >= 2 * qt) {
#pragma unroll
            for (int mi = 0; mi < 2; mi++)
#pragma unroll
                for (int nf = 0; nf < 8; nf++) {
                    int gc = kt * 64 + nf * 8 + 2 * (l & 3);
                    if (gc     > grow[mi * 2])     sc[mi][nf][0] = -1e30f;
                    if (gc + 1 > grow[mi * 2])     sc[mi][nf][1] = -1e30f;
                    if (gc     > grow[mi * 2 + 1]) sc[mi][nf][2] = -1e30f;
                    if (gc + 1 > grow[mi * 2 + 1]) sc[mi][nf][3] = -1e30f;
                }
        }

#pragma unroll
        for (int mi = 0; mi < 2; mi++) {
            float mx0 = -1e30f, mx1 = -1e30f;
#pragma unroll
            for (int nf = 0; nf < 8; nf++) {
                mx0 = fmaxf(mx0, fmaxf(sc[mi][nf][0], sc[mi][nf][1]));
                mx1 = fmaxf(mx1, fmaxf(sc[mi][nf][2], sc[mi][nf][3]));
            }
#pragma unroll
            for (int off = 1; off < 4; off <<= 1) {
                mx0 = fmaxf(mx0, __shfl_xor_sync(0xffffffffu, mx0, off));
                mx1 = fmaxf(mx1, __shfl_xor_sync(0xffffffffu, mx1, off));
            }
            float mn0 = fmaxf(mrow[mi * 2], mx0);
            float mn1 = fmaxf(mrow[mi * 2 + 1], mx1);
            float al0 = fexp2(mrow[mi * 2] - mn0);
            float al1 = fexp2(mrow[mi * 2 + 1] - mn1);
            mrow[mi * 2] = mn0; mrow[mi * 2 + 1] = mn1;

            float rs0 = 0.0f, rs1 = 0.0f;
#pragma unroll
            for (int nf = 0; nf < 8; nf++) {
                sc[mi][nf][0] = fexp2(sc[mi][nf][0] - mn0);
                sc[mi][nf][1] = fexp2(sc[mi][nf][1] - mn0);
                sc[mi][nf][2] = fexp2(sc[mi][nf][2] - mn1);
                sc[mi][nf][3] = fexp2(sc[mi][nf][3] - mn1);
                rs0 += sc[mi][nf][0] + sc[mi][nf][1];
                rs1 += sc[mi][nf][2] + sc[mi][nf][3];
            }
#pragma unroll
            for (int off = 1; off < 4; off <<= 1) {
                rs0 += __shfl_xor_sync(0xffffffffu, rs0, off);
                rs1 += __shfl_xor_sync(0xffffffffu, rs1, off);
            }
            lrow[mi * 2]     = lrow[mi * 2] * al0 + rs0;
            lrow[mi * 2 + 1] = lrow[mi * 2 + 1] * al1 + rs1;
#pragma unroll
            for (int nf = 0; nf < 8; nf++) {
                o[mi][nf][0] *= al0; o[mi][nf][1] *= al0;
                o[mi][nf][2] *= al1; o[mi][nf][3] *= al1;
            }
        }

        uint32_t ph[2][4][4];
#pragma unroll
        for (int mi = 0; mi < 2; mi++)
#pragma unroll
            for (int ks = 0; ks < 4; ks++) {
                ph[mi][ks][0] = pack_h2(sc[mi][2 * ks][0],     sc[mi][2 * ks][1]);
                ph[mi][ks][1] = pack_h2(sc[mi][2 * ks][2],     sc[mi][2 * ks][3]);
                ph[mi][ks][2] = pack_h2(sc[mi][2 * ks + 1][0], sc[mi][2 * ks + 1][1]);
                ph[mi][ks][3] = pack_h2(sc[mi][2 * ks + 1][2], sc[mi][2 * ks + 1][3]);
            }

#pragma unroll
        for (int ks = 0; ks < 4; ks++) {
#pragma unroll
            for (int np = 0; np < 4; np++) {
                uint32_t v4[4];
                ldsm_x4_t(v4, base + V_O + vsel
                              + (uint32_t)(ks * 16 * ARB + np * 32));
#pragma unroll
                for (int mi = 0; mi < 2; mi++) {
                    mma_f16(o[mi][2 * np],     ph[mi][ks], v4);
                    mma_f16(o[mi][2 * np + 1], ph[mi][ks], v4 + 2);
                }
            }
        }
    }

    const int b = bh >> 4, h = bh & 15;
#pragma unroll
    for (int mi = 0; mi < 2; mi++) {
        float inv0 = 1.0f / lrow[mi * 2], inv1 = 1.0f / lrow[mi * 2 + 1];
        size_t r0 = (size_t)(b * S_ + grow[mi * 2]) * (H_ * DH) + h * DH;
        size_t r1 = (size_t)(b * S_ + grow[mi * 2 + 1]) * (H_ * DH) + h * DH;
#pragma unroll
        for (int nf = 0; nf < 8; nf++) {
            int e = nf * 8 + 2 * (l & 3);
            *(uint32_t*)&g_atth[r0 + e] = pack_h2(o[mi][nf][0] * inv0,
                                                  o[mi][nf][1] * inv0);
            *(uint32_t*)&g_atth[r1 + e] = pack_h2(o[mi][nf][2] * inv1,
                                                  o[mi][nf][3] * inv1);
        }
    }
}

// ============================================================================
// O-projection via fp16 mma: out[8192,64] = att[8192,1024] @ Wo + bo
// 64-row CTAs, 128 threads (4 warps x 16-row tiles) -> grid 128, better
// latency overlap than the old grid-64 version.
// ============================================================================
#define OP_BW    5120        // B offset (A = 64 rows x 80B)
#define OP_STAGE 10240       // A 5120 + B 5120

__global__ __launch_bounds__(128) void oproj_mma_kernel(
    const float* __restrict__ bo, float* __restrict__ out)
{
    extern __shared__ __align__(128) char smem[];
    const uint32_t sb0 = smem_u32(smem);
    const int tid = threadIdx.x;
    const int w = tid >> 5, l = tid & 31;
    const int bm = blockIdx.x;           // 0..127 (64 rows each)
    const int arow0 = bm * 64;

    uint32_t aoff, boff[4];
    {
        int row = w * 16 + (l & 15);
        int col = ((l >> 4) & 1) * 8;
        aoff = (uint32_t)(row * ROWB + col * 2);
    }
#pragma unroll
    for (int bg = 0; bg < 4; bg++) {
        int nrow = bg * 16 + ((l >> 4) & 1) * 8 + (l & 7);
        int col = ((l >> 3) & 1) * 8;
        boff[bg] = (uint32_t)(nrow * ROWB + col * 2);
    }

    float acc[8][4];
#pragma unroll
    for (int j = 0; j < 8; j++)
#pragma unroll
        for (int q = 0; q < 4; q++) acc[j][q] = 0.0f;

    auto load_chunk = [&](int c, int s) {
        uint32_t base = sb0 + (uint32_t)s * OP_STAGE;
#pragma unroll
        for (int i = 0; i < 2; i++) {
            int slot = tid + i * 128;          // 0..255 : 64 rows x 4 kg
            int row = slot >> 2, kg = slot & 3;
            uint32_t so = (uint32_t)(row * ROWB + kg * 16);
            cp16(base + so,         g_atth + (size_t)(arow0 + row) * DIN + c * BK + kg * 8);
            cp16(base + OP_BW + so, g_woh + (size_t)row * DIN + c * BK + kg * 8);
        }
    };

    load_chunk(0, 0);
    CP_COMMIT();
    load_chunk(1, 1);
    CP_COMMIT();

    for (int c = 0; c < NCHUNK; c++) {
        int s = c % 3;
        if (c == NCHUNK - 1) { CP_WAIT(0); } else { CP_WAIT(1); }
        __syncthreads();

        uint32_t base = sb0 + (uint32_t)s * OP_STAGE;
#pragma unroll
        for (int ks = 0; ks < 2; ks++) {
            uint32_t kadd = (uint32_t)(ks * 32);
            uint32_t ah[4], bw[8][2];
            ldsm_x4(ah, base + aoff + kadd);
#pragma unroll
            for (int bg = 0; bg < 4; bg++) {
                uint32_t r[4];
                ldsm_x4(r, base + OP_BW + boff[bg] + kadd);
                bw[bg * 2][0] = r[0]; bw[bg * 2][1] = r[1];
                bw[bg * 2 + 1][0] = r[2]; bw[bg * 2 + 1][1] = r[3];
            }
#pragma unroll
            for (int ni = 0; ni < 8; ni++)
                mma_f16(acc[ni], ah, bw[ni]);
        }

        if (c + 2 < NCHUNK) {
            load_chunk(c + 2, (c + 2) % 3);
            CP_COMMIT();
        }
    }

    int m0 = arow0 + w * 16 + (l >> 2);
#pragma unroll
    for (int ni = 0; ni < 8; ni++) {
        int ncol = ni * 8 + 2 * (l & 3);
        float b0 = bo[ncol], b1 = bo[ncol + 1];
#pragma unroll
        for (int half = 0; half < 2; half++) {
            int m = m0 + half * 8;
            float2 v;
            v.x = acc[ni][half * 2 + 0] + b0;
            v.y = acc[ni][half * 2 + 1] + b1;
            *(float2*)&out[(size_t)m * DH + ncol] = v;
        }
    }
}

// ============================================================================
extern "C" void kernel_launch(void* const* d_in, const int* in_sizes, int n_in,
                              void* d_out, int out_size)
{
    const float* x  = (const float*)d_in[0];
    const float* Wq = (const float*)d_in[1];
    const float* bq = (const float*)d_in[2];
    const float* Wk = (const float*)d_in[3];
    const float* bk = (const float*)d_in[4];
    const float* Wv = (const float*)d_in[5];
    const float* bv = (const float*)d_in[6];
    const float* Wo = (const float*)d_in[7];
    const float* bo = (const float*)d_in[8];
    float* out = (float*)d_out;

    cudaFuncSetAttribute(qkv_mma_kernel, cudaFuncAttributeMaxDynamicSharedMemorySize,
                         3 * QSTAGE);
    cudaFuncSetAttribute(attn_mma_kernel, cudaFuncAttributeMaxDynamicSharedMemorySize,
                         ATT_SMEM);
    cudaFuncSetAttribute(oproj_mma_kernel, cudaFuncAttributeMaxDynamicSharedMemorySize,
                         3 * OP_STAGE);

    cvt_kernel<<<8976, 256>>>(x, Wq, Wk, Wv, Wo);
    qkv_mma_kernel<<<dim3(128, 24), 128, 3 * QSTAGE>>>(bq, bk, bv);
    attn_mma_kernel<<<dim3(64, 16), 128, ATT_SMEM>>>();
    oproj_mma_kernel<<<M_ / 64, 128, 3 * OP_STAGE>>>(bo, out);
}

// round 17
// speedup vs baseline: 1.0802x; 1.0126x over previous
#include <cuda_runtime.h>
#include <cuda_fp16.h>
#include <math.h>
#include <stdint.h>

#define B_   4
#define S_   2048
#define DIN  1024
#define H_   16
#define DH   64
#define M_   (B_ * S_)       // 8192
#define NTOT 3072
#define BH_  (B_ * H_)       // 64

// ---- scratch (device globals: allocation-free) ----
__device__ __half g_atth[M_ * H_ * DH];     // fp16 attention output [B*S, H*DH]

// fp16 attention operands, all [bh][s][e]
__device__ __half a_qh[BH_ * S_ * DH];      // pre-scaled by 0.125*log2(e)
__device__ __half a_kh[BH_ * S_ * DH];
__device__ __half a_vh[BH_ * S_ * DH];

// fp16 operands for QKV GEMM / O-proj
__device__ __half g_xh[M_ * DIN];
__device__ __half g_wh[NTOT * DIN];         // [n][k]
__device__ __half g_woh[DH * DIN];          // [n][k] for O-proj (n=64)

#define SCALE_LOG2E 0.18033688011112042591999058f  // 0.125 * log2(e)

// ============================================================================
// helpers
// ============================================================================
__device__ __forceinline__ uint32_t smem_u32(const void* p) {
    uint32_t a;
    asm("{ .reg .u64 t; cvta.to.shared.u64 t, %1; cvt.u32.u64 %0, t; }"
        : "=r"(a) : "l"(p));
    return a;
}
__device__ __forceinline__ void cp16(uint32_t dst, const void* src) {
    asm volatile("cp.async.cg.shared.global [%0], [%1], 16;" :: "r"(dst), "l"(src));
}
#define CP_COMMIT() asm volatile("cp.async.commit_group;" ::: "memory")
#define CP_WAIT(n)  asm volatile("cp.async.wait_group %0;" :: "n"(n) : "memory")

__device__ __forceinline__ void ldsm_x4(uint32_t* r, uint32_t addr) {
    asm volatile("ldmatrix.sync.aligned.m8n8.x4.shared.b16 {%0,%1,%2,%3}, [%4];"
                 : "=r"(r[0]), "=r"(r[1]), "=r"(r[2]), "=r"(r[3]) : "r"(addr));
}
__device__ __forceinline__ void ldsm_x4_t(uint32_t* r, uint32_t addr) {
    asm volatile("ldmatrix.sync.aligned.m8n8.x4.trans.shared.b16 {%0,%1,%2,%3}, [%4];"
                 : "=r"(r[0]), "=r"(r[1]), "=r"(r[2]), "=r"(r[3]) : "r"(addr));
}
__device__ __forceinline__ void mma_f16(float* c, const uint32_t* a, const uint32_t* b) {
    asm volatile(
        "mma.sync.aligned.m16n8k16.row.col.f32.f16.f16.f32 "
        "{%0,%1,%2,%3}, {%4,%5,%6,%7}, {%8,%9}, {%0,%1,%2,%3};"
        : "+f"(c[0]), "+f"(c[1]), "+f"(c[2]), "+f"(c[3])
        : "r"(a[0]), "r"(a[1]), "r"(a[2]), "r"(a[3]), "r"(b[0]), "r"(b[1]));
}

// exp2 on the MUFU pipe (1 instruction; frees FMA/ALU issue slots)
__device__ __forceinline__ float fexp2(float x) {
    float y;
    asm("ex2.approx.f32 %0, %1;" : "=f"(y) : "f"(x));
    return y;
}

__device__ __forceinline__ uint32_t pack_h2(float x, float y) {
    __half2 h = __floats2half2_rn(x, y);
    return *(uint32_t*)&h;
}

// ============================================================================
// merged conversion kernel:
//   blocks [0, 8192)        : convert X to fp16
//   blocks [8192, 8976)     : transpose+convert weights
//   blocks [8976, 9104)     : initialize out with bias (for split-K oproj)
// ============================================================================
__global__ __launch_bounds__(256) void cvt_kernel(
    const float* __restrict__ x,
    const float* __restrict__ Wq, const float* __restrict__ Wk,
    const float* __restrict__ Wv, const float* __restrict__ Wo,
    const float* __restrict__ bo, float* __restrict__ out) {
    __shared__ float t[64][65];
    const int tid = threadIdx.x;

    if (blockIdx.x < 8192) {
        int i = (blockIdx.x * 256 + tid) * 4;
        float4 v = *(const float4*)&x[i];
        *(uint32_t*)&g_xh[i]     = pack_h2(v.x, v.y);
        *(uint32_t*)&g_xh[i + 2] = pack_h2(v.z, v.w);
        return;
    }
    if (blockIdx.x >= 8976) {
        // out init: out[m][n] = bo[n]; each thread writes 16 consecutive floats
        int tI = (blockIdx.x - 8976) * 256 + tid;     // 0..32767
        size_t base = (size_t)tI * 16;
        int n0 = (int)(base & 63);
#pragma unroll
        for (int j = 0; j < 4; j++) {
            float4 v;
            v.x = bo[n0 + j * 4 + 0];
            v.y = bo[n0 + j * 4 + 1];
            v.z = bo[n0 + j * 4 + 2];
            v.w = bo[n0 + j * 4 + 3];
            *(float4*)&out[base + j * 4] = v;
        }
        return;
    }

    const int bid = blockIdx.x - 8192;       // 0..783
    const int kc = bid & 15, g = bid >> 4;

    const float* src;
    __half* dst;
    if (g < 48) {
        int part = g >> 4, h = g & 15;
        const float* Wp = (part == 0) ? Wq : (part == 1) ? Wk : Wv;
        src = Wp + (size_t)h * (DIN * DH) + (size_t)kc * 64 * DH;
        dst = g_wh + (size_t)(part * 1024 + h * 64) * DIN + kc * 64;
    } else {
        src = Wo + (size_t)kc * 64 * DH;
        dst = g_woh + kc * 64;
    }

#pragma unroll
    for (int i = 0; i < 16; i++) {
        int idx = tid + i * 256;
        int kk = idx >> 6, e = idx & 63;
        t[kk][e] = src[kk * DH + e];
    }
    __syncthreads();
#pragma unroll
    for (int i = 0; i < 16; i++) {
        int idx = tid + i * 256;
        int e = idx >> 6, kk = idx & 63;
        dst[(size_t)e * DIN + kk] = __float2half_rn(t[kk][e]);
    }
}

// ============================================================================
// QKV GEMM, single-pass fp16 mma. 128-thread CTAs, 64x128 tile, BK=32,
// 3-stage pipeline. Warp tile 64m x 32n. (validated winner, verbatim)
// ============================================================================
#define BK      32
#define NCHUNK  (DIN / BK)
#define ROWB    80
#define QA_SZ   5120           // 64 rows x 80B
#define QSTAGE  15360          // A 5120 + B 10240

__global__ __launch_bounds__(128) void qkv_mma_kernel(
    const float* __restrict__ bq, const float* __restrict__ bk,
    const float* __restrict__ bv)
{
    extern __shared__ __align__(128) char smem[];
    const uint32_t sb0 = smem_u32(smem);
    const int tid = threadIdx.x;
    const int wid = tid >> 5, l = tid & 31;
    const int wn = wid;                 // 1 x 4 warp grid
    const int bm = blockIdx.x;          // 0..127 (64 rows each)
    const int bn = blockIdx.y;          // 0..23

    const int arow0 = bm * 64, brow0 = bn * 128;

    uint32_t aoff[4], boff[2];
#pragma unroll
    for (int mi = 0; mi < 4; mi++) {
        int row = mi * 16 + (l & 15);
        int col = ((l >> 4) & 1) * 8;
        aoff[mi] = (uint32_t)(row * ROWB + col * 2);
    }
#pragma unroll
    for (int bg = 0; bg < 2; bg++) {
        int nrow = wn * 32 + bg * 16 + ((l >> 4) & 1) * 8 + (l & 7);
        int col = ((l >> 3) & 1) * 8;
        boff[bg] = (uint32_t)(nrow * ROWB + col * 2);
    }

    float acc[4][4][4];
#pragma unroll
    for (int i = 0; i < 4; i++)
#pragma unroll
        for (int j = 0; j < 4; j++)
#pragma unroll
            for (int q = 0; q < 4; q++) acc[i][j][q] = 0.0f;

    auto load_chunk = [&](int c, int s) {
        uint32_t base = sb0 + (uint32_t)s * QSTAGE;
#pragma unroll
        for (int i = 0; i < 2; i++) {
            int slot = tid + i * 128;          // 0..255 : A 64 rows x 4 kg
            int row = slot >> 2, kg = slot & 3;
            uint32_t so = (uint32_t)(row * ROWB + kg * 16);
            cp16(base + so, g_xh + (size_t)(arow0 + row) * DIN + c * BK + kg * 8);
        }
#pragma unroll
        for (int i = 0; i < 4; i++) {
            int slot = tid + i * 128;          // 0..511 : B 128 rows x 4 kg
            int row = slot >> 2, kg = slot & 3;
            uint32_t so = (uint32_t)(row * ROWB + kg * 16);
            cp16(base + QA_SZ + so, g_wh + (size_t)(brow0 + row) * DIN + c * BK + kg * 8);
        }
    };

    load_chunk(0, 0);
    CP_COMMIT();
    load_chunk(1, 1);
    CP_COMMIT();

    for (int c = 0; c < NCHUNK; c++) {
        int s = c % 3;
        if (c == NCHUNK - 1) { CP_WAIT(0); } else { CP_WAIT(1); }
        __syncthreads();

        uint32_t base = sb0 + (uint32_t)s * QSTAGE;
#pragma unroll
        for (int ks = 0; ks < 2; ks++) {
            uint32_t kadd = (uint32_t)(ks * 32);
            uint32_t ah[4][4], bw[4][2];
#pragma unroll
            for (int mi = 0; mi < 4; mi++)
                ldsm_x4(ah[mi], base + aoff[mi] + kadd);
#pragma unroll
            for (int bg = 0; bg < 2; bg++) {
                uint32_t r[4];
                ldsm_x4(r, base + QA_SZ + boff[bg] + kadd);
                bw[bg * 2][0] = r[0]; bw[bg * 2][1] = r[1];
                bw[bg * 2 + 1][0] = r[2]; bw[bg * 2 + 1][1] = r[3];
            }
#pragma unroll
            for (int mi = 0; mi < 4; mi++)
#pragma unroll
                for (int ni = 0; ni < 4; ni++)
                    mma_f16(acc[mi][ni], ah[mi], bw[ni]);
        }

        if (c + 2 < NCHUNK) {
            load_chunk(c + 2, (c + 2) % 3);
            CP_COMMIT();
        }
    }

    const int part = bn >> 3;
    const float* __restrict__ bp = (part == 0) ? bq : (part == 1) ? bk : bv;
    __half* __restrict__ oh = (part == 0) ? a_qh : (part == 1) ? a_kh : a_vh;
    const int npart0 = (bn & 7) * 128 + wn * 32;
    const float scl = (part == 0) ? SCALE_LOG2E : 1.0f;

#pragma unroll
    for (int mi = 0; mi < 4; mi++) {
        int m0 = arow0 + mi * 16 + (l >> 2);
#pragma unroll
        for (int ni = 0; ni < 4; ni++) {
            int ncol = npart0 + ni * 8 + 2 * (l & 3);
            int h = ncol >> 6, e = ncol & 63;
            float b0 = bp[h * DH + e], b1 = bp[h * DH + e + 1];
#pragma unroll
            for (int half = 0; half < 2; half++) {
                int m = m0 + half * 8;
                int bb = m >> 11, sIdx = m & 2047;
                float v0 = (acc[mi][ni][half * 2 + 0] + b0) * scl;
                float v1 = (acc[mi][ni][half * 2 + 1] + b1) * scl;
                size_t idx = (((size_t)bb * H_ + h) * S_ + sIdx) * DH + e;
                *(uint32_t*)&oh[idx] = pack_h2(v0, v1);
            }
        }
    }
}

// ============================================================================
// Causal flash attention: 128-thread CTAs, 128-row q-tiles, warp tile
// 32 rows x 64 keys (2 m-frags share every K/V fragment). (winner, verbatim)
// ============================================================================
#define ARB    144
#define Q_O    0
#define QT_B   18432
#define STG_O  18432
#define V_O    9216
#define STG_SZ 18432
#define ATT_SMEM (QT_B + 2 * STG_SZ)   // 55296

__global__ __launch_bounds__(128) void attn_mma_kernel()
{
    extern __shared__ __align__(128) char smem[];
    const uint32_t sb = smem_u32(smem);
    const int tid = threadIdx.x;
    const int w = tid >> 5, l = tid & 31;
    const int bh = blockIdx.x;
    const int qt = 15 - blockIdx.y;

    const __half* __restrict__ qh = a_qh + (size_t)bh * S_ * DH;
    const __half* __restrict__ kh = a_kh + (size_t)bh * S_ * DH;
    const __half* __restrict__ vh = a_vh + (size_t)bh * S_ * DH;

#pragma unroll
    for (int i = 0; i < 8; i++) {
        int idx = tid + i * 128;
        int row = idx >> 3, kg = idx & 7;
        uint32_t so = (uint32_t)(row * ARB + kg * 16);
        cp16(sb + Q_O + so, qh + (size_t)(qt * 128 + row) * DH + kg * 8);
    }

    auto load_kv = [&](int kt, int s) {
        uint32_t base = sb + STG_O + (uint32_t)s * STG_SZ;
#pragma unroll
        for (int i = 0; i < 4; i++) {
            int idx = tid + i * 128;
            int row = idx >> 3, kg = idx & 7;
            uint32_t so = (uint32_t)(row * ARB + kg * 16);
            size_t go = (size_t)(kt * 64 + row) * DH + kg * 8;
            cp16(base + so,       kh + go);
            cp16(base + V_O + so, vh + go);
        }
    };

    const int nkt = 2 * qt + 2;
    load_kv(0, 0);
    CP_COMMIT();

    float o[2][8][4];
#pragma unroll
    for (int mi = 0; mi < 2; mi++)
#pragma unroll
        for (int i = 0; i < 8; i++)
#pragma unroll
            for (int j = 0; j < 4; j++) o[mi][i][j] = 0.0f;
    float mrow[4] = {-1e30f, -1e30f, -1e30f, -1e30f};
    float lrow[4] = {0.0f, 0.0f, 0.0f, 0.0f};

    int grow[4];
#pragma unroll
    for (int mi = 0; mi < 2; mi++) {
        grow[mi * 2]     = qt * 128 + w * 32 + mi * 16 + (l >> 2);
        grow[mi * 2 + 1] = grow[mi * 2] + 8;
    }
    uint32_t qa0[2];
#pragma unroll
    for (int mi = 0; mi < 2; mi++)
        qa0[mi] = sb + Q_O + (uint32_t)((w * 32 + mi * 16 + (l & 15)) * ARB
                                        + ((l >> 4) & 1) * 16);
    const uint32_t bsel = (uint32_t)((8 * ((l >> 4) & 1) + (l & 7)) * ARB
                                     + ((l >> 3) & 1) * 16);
    const uint32_t vsel = (uint32_t)(((((l >> 3) & 1) * 8) + (l & 7)) * ARB
                                     + ((l >> 4) & 1) * 16);

    uint32_t qf[2][4][4];

    for (int kt = 0; kt < nkt; kt++) {
        int s = kt & 1;
        CP_WAIT(0);
        __syncthreads();
        if (kt == 0) {
#pragma unroll
            for (int mi = 0; mi < 2; mi++)
#pragma unroll
                for (int ks = 0; ks < 4; ks++)
                    ldsm_x4(qf[mi][ks], qa0[mi] + ks * 32);
        }
        if (kt + 1 < nkt) {
            load_kv(kt + 1, 1 - s);
            CP_COMMIT();
        }
        uint32_t base = sb + STG_O + (uint32_t)s * STG_SZ;

        float sc[2][8][4];
#pragma unroll
        for (int mi = 0; mi < 2; mi++)
#pragma unroll
            for (int i = 0; i < 8; i++)
#pragma unroll
                for (int j = 0; j < 4; j++) sc[mi][i][j] = 0.0f;

#pragma unroll
        for (int ks = 0; ks < 4; ks++) {
#pragma unroll
            for (int nfp = 0; nfp < 4; nfp++) {
                uint32_t k4[4];
                ldsm_x4(k4, base + bsel + (uint32_t)(nfp * 16 * ARB + ks * 32));
#pragma unroll
                for (int mi = 0; mi < 2; mi++) {
                    mma_f16(sc[mi][2 * nfp],     qf[mi][ks], k4);
                    mma_f16(sc[mi][2 * nfp + 1], qf[mi][ks], k4 + 2);
                }
            }
        }

        if (kt >= 2 * qt) {
#pragma unroll
            for (int mi = 0; mi < 2; mi++)
#pragma unroll
                for (int nf = 0; nf < 8; nf++) {
                    int gc = kt * 64 + nf * 8 + 2 * (l & 3);
                    if (gc     > grow[mi * 2])     sc[mi][nf][0] = -1e30f;
                    if (gc + 1 > grow[mi * 2])     sc[mi][nf][1] = -1e30f;
                    if (gc     > grow[mi * 2 + 1]) sc[mi][nf][2] = -1e30f;
                    if (gc + 1 > grow[mi * 2 + 1]) sc[mi][nf][3] = -1e30f;
                }
        }

#pragma unroll
        for (int mi = 0; mi < 2; mi++) {
            float mx0 = -1e30f, mx1 = -1e30f;
#pragma unroll
            for (int nf = 0; nf < 8; nf++) {
                mx0 = fmaxf(mx0, fmaxf(sc[mi][nf][0], sc[mi][nf][1]));
                mx1 = fmaxf(mx1, fmaxf(sc[mi][nf][2], sc[mi][nf][3]));
            }
#pragma unroll
            for (int off = 1; off < 4; off <<= 1) {
                mx0 = fmaxf(mx0, __shfl_xor_sync(0xffffffffu, mx0, off));
                mx1 = fmaxf(mx1, __shfl_xor_sync(0xffffffffu, mx1, off));
            }
            float mn0 = fmaxf(mrow[mi * 2], mx0);
            float mn1 = fmaxf(mrow[mi * 2 + 1], mx1);
            float al0 = fexp2(mrow[mi * 2] - mn0);
            float al1 = fexp2(mrow[mi * 2 + 1] - mn1);
            mrow[mi * 2] = mn0; mrow[mi * 2 + 1] = mn1;

            float rs0 = 0.0f, rs1 = 0.0f;
#pragma unroll
            for (int nf = 0; nf < 8; nf++) {
                sc[mi][nf][0] = fexp2(sc[mi][nf][0] - mn0);
                sc[mi][nf][1] = fexp2(sc[mi][nf][1] - mn0);
                sc[mi][nf][2] = fexp2(sc[mi][nf][2] - mn1);
                sc[mi][nf][3] = fexp2(sc[mi][nf][3] - mn1);
                rs0 += sc[mi][nf][0] + sc[mi][nf][1];
                rs1 += sc[mi][nf][2] + sc[mi][nf][3];
            }
#pragma unroll
            for (int off = 1; off < 4; off <<= 1) {
                rs0 += __shfl_xor_sync(0xffffffffu, rs0, off);
                rs1 += __shfl_xor_sync(0xffffffffu, rs1, off);
            }
            lrow[mi * 2]     = lrow[mi * 2] * al0 + rs0;
            lrow[mi * 2 + 1] = lrow[mi * 2 + 1] * al1 + rs1;
#pragma unroll
            for (int nf = 0; nf < 8; nf++) {
                o[mi][nf][0] *= al0; o[mi][nf][1] *= al0;
                o[mi][nf][2] *= al1; o[mi][nf][3] *= al1;
            }
        }

        uint32_t ph[2][4][4];
#pragma unroll
        for (int mi = 0; mi < 2; mi++)
#pragma unroll
            for (int ks = 0; ks < 4; ks++) {
                ph[mi][ks][0] = pack_h2(sc[mi][2 * ks][0],     sc[mi][2 * ks][1]);
                ph[mi][ks][1] = pack_h2(sc[mi][2 * ks][2],     sc[mi][2 * ks][3]);
                ph[mi][ks][2] = pack_h2(sc[mi][2 * ks + 1][0], sc[mi][2 * ks + 1][1]);
                ph[mi][ks][3] = pack_h2(sc[mi][2 * ks + 1][2], sc[mi][2 * ks + 1][3]);
            }

#pragma unroll
        for (int ks = 0; ks < 4; ks++) {
#pragma unroll
            for (int np = 0; np < 4; np++) {
                uint32_t v4[4];
                ldsm_x4_t(v4, base + V_O + vsel
                              + (uint32_t)(ks * 16 * ARB + np * 32));
#pragma unroll
                for (int mi = 0; mi < 2; mi++) {
                    mma_f16(o[mi][2 * np],     ph[mi][ks], v4);
                    mma_f16(o[mi][2 * np + 1], ph[mi][ks], v4 + 2);
                }
            }
        }
    }

    const int b = bh >> 4, h = bh & 15;
#pragma unroll
    for (int mi = 0; mi < 2; mi++) {
        float inv0 = 1.0f / lrow[mi * 2], inv1 = 1.0f / lrow[mi * 2 + 1];
        size_t r0 = (size_t)(b * S_ + grow[mi * 2]) * (H_ * DH) + h * DH;
        size_t r1 = (size_t)(b * S_ + grow[mi * 2 + 1]) * (H_ * DH) + h * DH;
#pragma unroll
        for (int nf = 0; nf < 8; nf++) {
            int e = nf * 8 + 2 * (l & 3);
            *(uint32_t*)&g_atth[r0 + e] = pack_h2(o[mi][nf][0] * inv0,
                                                  o[mi][nf][1] * inv0);
            *(uint32_t*)&g_atth[r1 + e] = pack_h2(o[mi][nf][2] * inv1,
                                                  o[mi][nf][3] * inv1);
        }
    }
}

// ============================================================================
// O-projection via fp16 mma, SPLIT-K x4: grid (128 m, 4 ksplit).
// Each CTA accumulates 8 k-chunks and atomicAdds into bias-initialized out.
// ============================================================================
#define OP_BW    5120        // B offset (A = 64 rows x 80B)
#define OP_STAGE 10240       // A 5120 + B 5120
#define KSPLIT   4
#define OPNCH    (NCHUNK / KSPLIT)   // 8

__global__ __launch_bounds__(128) void oproj_mma_kernel(float* __restrict__ out)
{
    extern __shared__ __align__(128) char smem[];
    const uint32_t sb0 = smem_u32(smem);
    const int tid = threadIdx.x;
    const int w = tid >> 5, l = tid & 31;
    const int bm = blockIdx.x;           // 0..127 (64 rows each)
    const int c0 = blockIdx.y * OPNCH;   // k-chunk base
    const int arow0 = bm * 64;

    uint32_t aoff, boff[4];
    {
        int row = w * 16 + (l & 15);
        int col = ((l >> 4) & 1) * 8;
        aoff = (uint32_t)(row * ROWB + col * 2);
    }
#pragma unroll
    for (int bg = 0; bg < 4; bg++) {
        int nrow = bg * 16 + ((l >> 4) & 1) * 8 + (l & 7);
        int col = ((l >> 3) & 1) * 8;
        boff[bg] = (uint32_t)(nrow * ROWB + col * 2);
    }

    float acc[8][4];
#pragma unroll
    for (int j = 0; j < 8; j++)
#pragma unroll
        for (int q = 0; q < 4; q++) acc[j][q] = 0.0f;

    auto load_chunk = [&](int c, int s) {
        uint32_t base = sb0 + (uint32_t)s * OP_STAGE;
#pragma unroll
        for (int i = 0; i < 2; i++) {
            int slot = tid + i * 128;          // 0..255 : 64 rows x 4 kg
            int row = slot >> 2, kg = slot & 3;
            uint32_t so = (uint32_t)(row * ROWB + kg * 16);
            cp16(base + so,         g_atth + (size_t)(arow0 + row) * DIN + c * BK + kg * 8);
            cp16(base + OP_BW + so, g_woh + (size_t)row * DIN + c * BK + kg * 8);
        }
    };

    load_chunk(c0, 0);
    CP_COMMIT();
    load_chunk(c0 + 1, 1);
    CP_COMMIT();

    for (int ci = 0; ci < OPNCH; ci++) {
        int s = ci % 3;
        if (ci == OPNCH - 1) { CP_WAIT(0); } else { CP_WAIT(1); }
        __syncthreads();

        uint32_t base = sb0 + (uint32_t)s * OP_STAGE;
#pragma unroll
        for (int ks = 0; ks < 2; ks++) {
            uint32_t kadd = (uint32_t)(ks * 32);
            uint32_t ah[4], bw[8][2];
            ldsm_x4(ah, base + aoff + kadd);
#pragma unroll
            for (int bg = 0; bg < 4; bg++) {
                uint32_t r[4];
                ldsm_x4(r, base + OP_BW + boff[bg] + kadd);
                bw[bg * 2][0] = r[0]; bw[bg * 2][1] = r[1];
                bw[bg * 2 + 1][0] = r[2]; bw[bg * 2 + 1][1] = r[3];
            }
#pragma unroll
            for (int ni = 0; ni < 8; ni++)
                mma_f16(acc[ni], ah, bw[ni]);
        }

        if (ci + 2 < OPNCH) {
            load_chunk(c0 + ci + 2, (ci + 2) % 3);
            CP_COMMIT();
        }
    }

    int m0 = arow0 + w * 16 + (l >> 2);
#pragma unroll
    for (int ni = 0; ni < 8; ni++) {
        int ncol = ni * 8 + 2 * (l & 3);
#pragma unroll
        for (int half = 0; half < 2; half++) {
            int m = m0 + half * 8;
            atomicAdd(&out[(size_t)m * DH + ncol],     acc[ni][half * 2 + 0]);
            atomicAdd(&out[(size_t)m * DH + ncol + 1], acc[ni][half * 2 + 1]);
        }
    }
}

// ============================================================================
extern "C" void kernel_launch(void* const* d_in, const int* in_sizes, int n_in,
                              void* d_out, int out_size)
{
    const float* x  = (const float*)d_in[0];
    const float* Wq = (const float*)d_in[1];
    const float* bq = (const float*)d_in[2];
    const float* Wk = (const float*)d_in[3];
    const float* bk = (const float*)d_in[4];
    const float* Wv = (const float*)d_in[5];
    const float* bv = (const float*)d_in[6];
    const float* Wo = (const float*)d_in[7];
    const float* bo = (const float*)d_in[8];
    float* out = (float*)d_out;

    cudaFuncSetAttribute(qkv_mma_kernel, cudaFuncAttributeMaxDynamicSharedMemorySize,
                         3 * QSTAGE);
    cudaFuncSetAttribute(attn_mma_kernel, cudaFuncAttributeMaxDynamicSharedMemorySize,
                         ATT_SMEM);
    cudaFuncSetAttribute(oproj_mma_kernel, cudaFuncAttributeMaxDynamicSharedMemorySize,
                         3 * OP_STAGE);

    cvt_kernel<<<9104, 256>>>(x, Wq, Wk, Wv, Wo, bo, out);
    qkv_mma_kernel<<<dim3(128, 24), 128, 3 * QSTAGE>>>(bq, bk, bv);
    attn_mma_kernel<<<dim3(64, 16), 128, ATT_SMEM>>>();
    oproj_mma_kernel<<<dim3(128, KSPLIT), 128, 3 * OP_STAGE>>>(out);
}